// round 14
// baseline (speedup 1.0000x reference)
#include <cuda_runtime.h>

// HaversineSmoothedLoss — R13 loop + perfectly balanced 592-block schedule.
//   a  = (1 - u1·u2)/2            (unit 3-vectors; no per-pair trig)
//   w  = exp2( -sqrt(|a*K^2|) )   K = (2*6371/75)*log2(e)
//   loss_b = log(Z_b) - (Σ w·x)/S_b ,  Z = Σ e^x, S = Σ w
//
// Work = 128 row-groups × 8192 quad-cols = 1,048,576 units. Block b owns the
// contiguous unit range [b*NU/592,(b+1)*NU/592): every block ±1 unit of fair
// share, grid = 148 SM × 4 blocks = one exact wave. A block crosses at most
// one row-group boundary -> <=2 segment flushes into fixed [row][slot] cells
// (slot = bid - first block of that rg; <=6 blocks touch one rg). Last block
// (arrival counter) reduces partials to the loss.

#define C_CELLS 32768
#define B_ROWS  512
#define RPB     4
#define QC      (C_CELLS / 4)            // 8192 quad-columns
#define NRG     (B_ROWS / RPB)           // 128 row groups
#define NU      (NRG * QC)               // 1048576 units
#define THREADS 256
#define NWARPS  (THREADS / 32)           // 8
#define GRID    592                      // 148 SMs x 4 blocks
#define NSLOT   8                        // >= max blocks touching one rg (6)

__device__ float4 d_ct[QC * 3];          // interleaved: quad q -> gx4,gy4,gz4
__device__ float  d_prow[3][B_ROWS];     // -0.5 * row unit vectors
__device__ float  d_pZ[B_ROWS][NSLOT];   // zero-init; unused slots stay 0
__device__ float  d_pS[B_ROWS][NSLOT];
__device__ float  d_pW[B_ROWS][NSLOT];
__device__ unsigned int d_ctr = 0;

__device__ __forceinline__ float fsqrt_ap(float a) {
    float r; asm("sqrt.approx.f32 %0, %1;" : "=f"(r) : "f"(a)); return r;
}
__device__ __forceinline__ float fexp2_ap(float a) {
    float r; asm("ex2.approx.f32 %0, %1;" : "=f"(r) : "f"(a)); return r;
}

__global__ void precompute(const float* __restrict__ geo,
                           const float* __restrict__ latlon) {
    const float d2r = 0.017453292519943295f;
    int i = blockIdx.x * blockDim.x + threadIdx.x;
    if (i < C_CELLS) {
        float lat = geo[2 * i]     * d2r;
        float lon = geo[2 * i + 1] * d2r;
        float sl, cl, so, co;
        sincosf(lat, &sl, &cl);
        sincosf(lon, &so, &co);
        const int q = i >> 2, k = i & 3;
        float* ct = (float*)d_ct;
        ct[q * 12 + 0 + k] = sl;        // gx
        ct[q * 12 + 4 + k] = cl * so;   // gy
        ct[q * 12 + 8 + k] = cl * co;   // gz
    }
    if (i < B_ROWS) {
        float lat = latlon[2 * i]     * d2r;
        float lon = latlon[2 * i + 1] * d2r;
        float sl, cl, so, co;
        sincosf(lat, &sl, &cl);
        sincosf(lon, &so, &co);
        d_prow[0][i] = -0.5f * sl;
        d_prow[1][i] = -0.5f * cl * so;
        d_prow[2][i] = -0.5f * cl * co;
    }
}

__global__ __launch_bounds__(THREADS, 4)
void main_kernel(const float* __restrict__ logits,
                 float* __restrict__ out) {
    const int bid = blockIdx.x;
    const int tid = threadIdx.x;

    const float LOG2E = 1.4426950408889634f;
    const float KL2   = 60076.13f;       // ((2*6371/75)*log2(e))^2

    // This block's contiguous unit range [u0, uend).
    int u0   = (int)(((long long)bid       * NU) / GRID);
    int uend = (int)(((long long)(bid + 1) * NU) / GRID);

    __shared__ float red[3 * RPB][NWARPS];
    const int lane = tid & 31, warp = tid >> 5;
    const float4* __restrict__ lg4 = (const float4*)logits;

    int u = u0;
    while (u < uend) {
        const int rg      = u >> 13;                    // u / QC
        const int seg_end = min(uend, (rg + 1) << 13);
        const int row0    = rg * RPB;

        // Row uniforms for this segment.
        float nx[RPB], ny[RPB], nz[RPB];
        #pragma unroll
        for (int r = 0; r < RPB; r++) {
            nx[r] = d_prow[0][row0 + r];
            ny[r] = d_prow[1][row0 + r];
            nz[r] = d_prow[2][row0 + r];
        }

        float Z[RPB], S[RPB], WX[RPB];
        #pragma unroll
        for (int r = 0; r < RPB; r++) { Z[r] = 0.f; S[r] = 0.f; WX[r] = 0.f; }

        for (int base = u; base < seg_end; base += THREADS) {
            const int q = base + tid;
            if (q < seg_end) {
                const int qcol = q - (rg << 13);

                // Front-batch all 7 LDG.128.
                float4 xr[RPB];
                #pragma unroll
                for (int r = 0; r < RPB; r++)
                    xr[r] = __ldg(lg4 + (size_t)(row0 + r) * QC + qcol);
                const float4 gx = __ldg(d_ct + (size_t)qcol * 3 + 0);
                const float4 gy = __ldg(d_ct + (size_t)qcol * 3 + 1);
                const float4 gz = __ldg(d_ct + (size_t)qcol * 3 + 2);

                const float gxs[4] = {gx.x, gx.y, gx.z, gx.w};
                const float gys[4] = {gy.x, gy.y, gy.z, gy.w};
                const float gzs[4] = {gz.x, gz.y, gz.z, gz.w};

                #pragma unroll
                for (int r = 0; r < RPB; r++) {
                    const float xs[4] = {xr[r].x, xr[r].y, xr[r].z, xr[r].w};
                    #pragma unroll
                    for (int k = 0; k < 4; k++) {
                        const float x = xs[k];
                        Z[r] += fexp2_ap(x * LOG2E);
                        float a = fmaf(nx[r], gxs[k],
                                  fmaf(ny[r], gys[k],
                                  fmaf(nz[r], gzs[k], 0.5f)));
                        float t = a * KL2;               // FMUL-imm
                        float s = fsqrt_ap(fabsf(t));
                        float w = fexp2_ap(-s);          // underflow -> 0 far away
                        S[r]  += w;
                        WX[r]  = fmaf(w, x, WX[r]);
                    }
                }
            }
        }

        // ---- Segment flush: block reduction into [row][slot] ----
        // first block touching rg: smallest b with s_b <= rg*QC.
        const int first_b = (int)((((long long)rg << 13) * GRID + (GRID - 1)) / NU);
        const int slot    = bid - first_b;               // 0..NSLOT-1

        float acc[3 * RPB];
        #pragma unroll
        for (int r = 0; r < RPB; r++) {
            acc[r * 3 + 0] = Z[r]; acc[r * 3 + 1] = S[r]; acc[r * 3 + 2] = WX[r];
        }
        __syncthreads();                 // red[] reuse across segments
        #pragma unroll
        for (int i = 0; i < 3 * RPB; i++) {
            float vv = acc[i];
            #pragma unroll
            for (int o = 16; o > 0; o >>= 1) vv += __shfl_down_sync(0xffffffffu, vv, o);
            if (lane == 0) red[i][warp] = vv;
        }
        __syncthreads();
        if (tid < 3 * RPB) {
            float vv = 0.f;
            #pragma unroll
            for (int wi = 0; wi < NWARPS; wi++) vv += red[tid][wi];
            const int r     = tid / 3;
            const int which = tid % 3;
            if      (which == 0) d_pZ[row0 + r][slot] = vv;
            else if (which == 1) d_pS[row0 + r][slot] = vv;
            else                 d_pW[row0 + r][slot] = vv;
        }

        u = seg_end;
    }

    // ---- Last block reduces everything ----
    __shared__ bool isLast;
    __syncthreads();
    if (tid == 0) {
        __threadfence();
        unsigned int t = atomicAdd(&d_ctr, 1u);
        isLast = (t == (unsigned int)(GRID - 1));
    }
    __syncthreads();

    if (isLast) {
        float v = 0.f;
        #pragma unroll
        for (int half = 0; half < B_ROWS / THREADS; half++) {   // 2 rows/thread
            const int b = tid + half * THREADS;
            float Zt = 0.f, St = 0.f, Wt = 0.f;
            #pragma unroll
            for (int sl = 0; sl < NSLOT; sl++) {
                Zt += __ldcg(&d_pZ[b][sl]);
                St += __ldcg(&d_pS[b][sl]);
                Wt += __ldcg(&d_pW[b][sl]);
            }
            v += logf(Zt) - Wt * __fdividef(1.0f, St);
        }
        __shared__ float fin[NWARPS];
        #pragma unroll
        for (int o = 16; o > 0; o >>= 1) v += __shfl_down_sync(0xffffffffu, v, o);
        if (lane == 0) fin[warp] = v;
        __syncthreads();
        if (tid == 0) {
            float s = 0.f;
            #pragma unroll
            for (int i = 0; i < NWARPS; i++) s += fin[i];
            out[0] = s * (1.0f / (float)B_ROWS);
            d_ctr  = 0;   // reset for graph replay
        }
    }
}

extern "C" void kernel_launch(void* const* d_in, const int* in_sizes, int n_in,
                              void* d_out, int out_size) {
    const float* logits = (const float*)d_in[0];   // [512, 32768]
    const float* latlon = (const float*)d_in[1];   // [512, 2]
    const float* geo    = (const float*)d_in[2];   // [32768, 2]

    precompute<<<(C_CELLS + 255) / 256, 256>>>(geo, latlon);
    main_kernel<<<GRID, THREADS>>>(logits, (float*)d_out);
}

// round 15
// speedup vs baseline: 1.0141x; 1.0141x over previous
#include <cuda_runtime.h>

// HaversineSmoothedLoss — R13 (best) + streaming logits loads + unroll-2 ILP.
//   a  = (1 - u1·u2)/2            (unit 3-vectors; no per-pair trig)
//   w  = exp2( -sqrt(|a*K^2|) )   K = (2*6371/75)*log2(e)
//   loss_b = log(Z_b) - (Σ w·x)/S_b ,  Z = Σ e^x, S = Σ w
//
// K0: interleaved celltab [gx4,gy4,gz4] per quad (48B stride) + row normals.
// K1: 512 blocks (256 thr) = 128 row-groups (4 rows) × 4 chunks (8192 cells),
//     8 iters/thread (unroll 2), 7 front-batched LDG.128/iter via advancing
//     pointers, logits streamed with .cs (read-once), branchless loop.
//     Last block (arrival counter) reduces partials.

#define C_CELLS 32768
#define B_ROWS  512
#define RPB     4
#define SPLIT   4
#define CHUNK   (C_CELLS / SPLIT)          // 8192
#define THREADS 256
#define NWARPS  (THREADS / 32)             // 8
#define ITERS   (CHUNK / (4 * THREADS))    // 8
#define GRID    ((B_ROWS / RPB) * SPLIT)   // 512

__device__ float4 d_ct[(C_CELLS / 4) * 3]; // interleaved: quad q -> gx4,gy4,gz4
__device__ float  d_prow[3][B_ROWS];       // -0.5 * row unit vectors
__device__ float  d_pZ[B_ROWS * SPLIT];
__device__ float  d_pS[B_ROWS * SPLIT];
__device__ float  d_pW[B_ROWS * SPLIT];
__device__ unsigned int d_ctr = 0;

__device__ __forceinline__ float fsqrt_ap(float a) {
    float r; asm("sqrt.approx.f32 %0, %1;" : "=f"(r) : "f"(a)); return r;
}
__device__ __forceinline__ float fexp2_ap(float a) {
    float r; asm("ex2.approx.f32 %0, %1;" : "=f"(r) : "f"(a)); return r;
}

__global__ void precompute(const float* __restrict__ geo,
                           const float* __restrict__ latlon) {
    const float d2r = 0.017453292519943295f;
    int i = blockIdx.x * blockDim.x + threadIdx.x;
    if (i < C_CELLS) {
        float lat = geo[2 * i]     * d2r;
        float lon = geo[2 * i + 1] * d2r;
        float sl, cl, so, co;
        sincosf(lat, &sl, &cl);
        sincosf(lon, &so, &co);
        const int q = i >> 2, k = i & 3;
        float* ct = (float*)d_ct;
        ct[q * 12 + 0 + k] = sl;        // gx
        ct[q * 12 + 4 + k] = cl * so;   // gy
        ct[q * 12 + 8 + k] = cl * co;   // gz
    }
    if (i < B_ROWS) {
        float lat = latlon[2 * i]     * d2r;
        float lon = latlon[2 * i + 1] * d2r;
        float sl, cl, so, co;
        sincosf(lat, &sl, &cl);
        sincosf(lon, &so, &co);
        d_prow[0][i] = -0.5f * sl;
        d_prow[1][i] = -0.5f * cl * so;
        d_prow[2][i] = -0.5f * cl * co;
    }
}

__global__ __launch_bounds__(THREADS, 4)
void main_kernel(const float* __restrict__ logits,
                 float* __restrict__ out) {
    const int bx    = blockIdx.x;
    const int rg    = bx >> 2;             // row group 0..127
    const int ch    = bx & (SPLIT - 1);    // chunk 0..3
    const int row0  = rg * RPB;
    const int tid   = threadIdx.x;
    const int q0    = ((ch * CHUNK) >> 2) + tid;   // this thread's first quad

    const float LOG2E = 1.4426950408889634f;
    const float KL2   = 60076.13f;         // ((2*6371/75)*log2(e))^2

    // Row uniforms (block-uniform loads).
    float nx[RPB], ny[RPB], nz[RPB];
    #pragma unroll
    for (int r = 0; r < RPB; r++) {
        nx[r] = d_prow[0][row0 + r];
        ny[r] = d_prow[1][row0 + r];
        nz[r] = d_prow[2][row0 + r];
    }

    // Advancing pointers: constant strides, loop-invariant address math.
    const float4* __restrict__ pct = d_ct + (size_t)q0 * 3;
    const float4* __restrict__ plg = (const float4*)logits + (size_t)row0 * (C_CELLS / 4) + q0;

    float Z[RPB], S[RPB], WX[RPB];
    #pragma unroll
    for (int r = 0; r < RPB; r++) { Z[r] = 0.f; S[r] = 0.f; WX[r] = 0.f; }

    #pragma unroll 2
    for (int it = 0; it < ITERS; it++) {
        // Front-batch all 7 LDG.128 (rows at fixed 8192-quad strides).
        // Logits: streaming (read exactly once) — keep L2 for the celltab.
        float4 xr[RPB];
        #pragma unroll
        for (int r = 0; r < RPB; r++)
            xr[r] = __ldcs(plg + (size_t)r * (C_CELLS / 4));
        const float4 gx = __ldg(pct + 0);
        const float4 gy = __ldg(pct + 1);
        const float4 gz = __ldg(pct + 2);
        pct += 3 * THREADS;
        plg += THREADS;

        const float gxs[4] = {gx.x, gx.y, gx.z, gx.w};
        const float gys[4] = {gy.x, gy.y, gy.z, gy.w};
        const float gzs[4] = {gz.x, gz.y, gz.z, gz.w};

        #pragma unroll
        for (int r = 0; r < RPB; r++) {
            const float xs[4] = {xr[r].x, xr[r].y, xr[r].z, xr[r].w};
            #pragma unroll
            for (int k = 0; k < 4; k++) {
                const float x = xs[k];
                Z[r] += fexp2_ap(x * LOG2E);
                float a = fmaf(nx[r], gxs[k], fmaf(ny[r], gys[k], fmaf(nz[r], gzs[k], 0.5f)));
                float t = a * KL2;                   // FMUL-imm (rt 1)
                float s = fsqrt_ap(fabsf(t));        // |t|: free MUFU modifier
                float w = fexp2_ap(-s);              // neg folded into MUFU operand
                S[r]  += w;
                WX[r]  = fmaf(w, x, WX[r]);
            }
        }
    }

    // ---- Block reduction of 12 accumulators (deterministic tree) ----
    float acc[3 * RPB];
    #pragma unroll
    for (int r = 0; r < RPB; r++) {
        acc[r * 3 + 0] = Z[r]; acc[r * 3 + 1] = S[r]; acc[r * 3 + 2] = WX[r];
    }
    __shared__ float red[3 * RPB][NWARPS];
    const int lane = tid & 31, warp = tid >> 5;
    #pragma unroll
    for (int i = 0; i < 3 * RPB; i++) {
        float vv = acc[i];
        #pragma unroll
        for (int o = 16; o > 0; o >>= 1) vv += __shfl_down_sync(0xffffffffu, vv, o);
        if (lane == 0) red[i][warp] = vv;
    }
    __syncthreads();
    if (tid < 3 * RPB) {
        float vv = 0.f;
        #pragma unroll
        for (int wi = 0; wi < NWARPS; wi++) vv += red[tid][wi];
        const int r     = tid / 3;
        const int which = tid % 3;
        const int idx   = (row0 + r) * SPLIT + ch;
        if      (which == 0) d_pZ[idx] = vv;
        else if (which == 1) d_pS[idx] = vv;
        else                 d_pW[idx] = vv;
    }

    // ---- Last block reduces everything ----
    __shared__ bool isLast;
    __syncthreads();
    if (tid == 0) {
        __threadfence();
        unsigned int t = atomicAdd(&d_ctr, 1u);
        isLast = (t == (unsigned int)(GRID - 1));
    }
    __syncthreads();

    if (isLast) {
        float v = 0.f;
        #pragma unroll
        for (int half = 0; half < B_ROWS / THREADS; half++) {   // 2 rows/thread
            const int b = tid + half * THREADS;
            float Zt = 0.f, St = 0.f, Wt = 0.f;
            #pragma unroll
            for (int cc = 0; cc < SPLIT; cc++) {
                Zt += __ldcg(&d_pZ[b * SPLIT + cc]);
                St += __ldcg(&d_pS[b * SPLIT + cc]);
                Wt += __ldcg(&d_pW[b * SPLIT + cc]);
            }
            v += logf(Zt) - Wt * __fdividef(1.0f, St);
        }
        __shared__ float fin[NWARPS];
        #pragma unroll
        for (int o = 16; o > 0; o >>= 1) v += __shfl_down_sync(0xffffffffu, v, o);
        if (lane == 0) fin[warp] = v;
        __syncthreads();
        if (tid == 0) {
            float s = 0.f;
            #pragma unroll
            for (int i = 0; i < NWARPS; i++) s += fin[i];
            out[0] = s * (1.0f / (float)B_ROWS);
            d_ctr  = 0;   // reset for graph replay
        }
    }
}

extern "C" void kernel_launch(void* const* d_in, const int* in_sizes, int n_in,
                              void* d_out, int out_size) {
    const float* logits = (const float*)d_in[0];   // [512, 32768]
    const float* latlon = (const float*)d_in[1];   // [512, 2]
    const float* geo    = (const float*)d_in[2];   // [32768, 2]

    precompute<<<(C_CELLS + 255) / 256, 256>>>(geo, latlon);
    main_kernel<<<GRID, THREADS>>>(logits, (float*)d_out);
}

// round 16
// speedup vs baseline: 1.0408x; 1.0263x over previous
#include <cuda_runtime.h>

// HaversineSmoothedLoss — R13 + K^2 folded into row normals + arrayless inner body.
//   a' = K^2*(1 - u1·u2)/2 computed directly: a' = n'·u2 + H', n' = -0.5K^2*u1,
//        H' = 0.5K^2   (K = (2*6371/75)*log2(e))
//   w  = exp2( -sqrt(|a'|) )
//   loss_b = log(Z_b) - (Σ w·x)/S_b ,  Z = Σ e^x, S = Σ w
//
// K0: interleaved celltab [gx4,gy4,gz4] per quad (48B stride) + scaled row normals.
// K1: 512 blocks (256 thr) = 128 row-groups (4 rows) × 4 chunks (8192 cells),
//     8 iters/thread, 7 front-batched LDG.128/iter via advancing pointers,
//     branchless 10-inst/elem loop. Last block (arrival counter) reduces partials.

#define C_CELLS 32768
#define B_ROWS  512
#define RPB     4
#define SPLIT   4
#define CHUNK   (C_CELLS / SPLIT)          // 8192
#define THREADS 256
#define NWARPS  (THREADS / 32)             // 8
#define ITERS   (CHUNK / (4 * THREADS))    // 8
#define GRID    ((B_ROWS / RPB) * SPLIT)   // 512

__device__ float4 d_ct[(C_CELLS / 4) * 3]; // interleaved: quad q -> gx4,gy4,gz4
__device__ float  d_prow[3][B_ROWS];       // -0.5*K^2 * row unit vectors
__device__ float  d_pZ[B_ROWS * SPLIT];
__device__ float  d_pS[B_ROWS * SPLIT];
__device__ float  d_pW[B_ROWS * SPLIT];
__device__ unsigned int d_ctr = 0;

__device__ __forceinline__ float fsqrt_ap(float a) {
    float r; asm("sqrt.approx.f32 %0, %1;" : "=f"(r) : "f"(a)); return r;
}
__device__ __forceinline__ float fexp2_ap(float a) {
    float r; asm("ex2.approx.f32 %0, %1;" : "=f"(r) : "f"(a)); return r;
}

__global__ void precompute(const float* __restrict__ geo,
                           const float* __restrict__ latlon) {
    const float d2r = 0.017453292519943295f;
    const float KL2 = 60076.13f;           // ((2*6371/75)*log2(e))^2
    int i = blockIdx.x * blockDim.x + threadIdx.x;
    if (i < C_CELLS) {
        float lat = geo[2 * i]     * d2r;
        float lon = geo[2 * i + 1] * d2r;
        float sl, cl, so, co;
        sincosf(lat, &sl, &cl);
        sincosf(lon, &so, &co);
        const int q = i >> 2, k = i & 3;
        float* ct = (float*)d_ct;
        ct[q * 12 + 0 + k] = sl;        // gx
        ct[q * 12 + 4 + k] = cl * so;   // gy
        ct[q * 12 + 8 + k] = cl * co;   // gz
    }
    if (i < B_ROWS) {
        float lat = latlon[2 * i]     * d2r;
        float lon = latlon[2 * i + 1] * d2r;
        float sl, cl, so, co;
        sincosf(lat, &sl, &cl);
        sincosf(lon, &so, &co);
        d_prow[0][i] = -0.5f * KL2 * sl;
        d_prow[1][i] = -0.5f * KL2 * cl * so;
        d_prow[2][i] = -0.5f * KL2 * cl * co;
    }
}

__global__ __launch_bounds__(THREADS, 4)
void main_kernel(const float* __restrict__ logits,
                 float* __restrict__ out) {
    const int bx    = blockIdx.x;
    const int rg    = bx >> 2;             // row group 0..127
    const int ch    = bx & (SPLIT - 1);    // chunk 0..3
    const int row0  = rg * RPB;
    const int tid   = threadIdx.x;
    const int q0    = ((ch * CHUNK) >> 2) + tid;   // this thread's first quad

    const float LOG2E = 1.4426950408889634f;
    const float HALFK = 30038.065f;        // 0.5 * KL2

    // Row uniforms (block-uniform loads), pre-scaled by -0.5*K^2.
    float nx[RPB], ny[RPB], nz[RPB];
    #pragma unroll
    for (int r = 0; r < RPB; r++) {
        nx[r] = d_prow[0][row0 + r];
        ny[r] = d_prow[1][row0 + r];
        nz[r] = d_prow[2][row0 + r];
    }

    // Advancing pointers: constant strides, loop-invariant address math.
    const float4* __restrict__ pct = d_ct + (size_t)q0 * 3;
    const float4* __restrict__ plg = (const float4*)logits + (size_t)row0 * (C_CELLS / 4) + q0;

    float Z[RPB], S[RPB], WX[RPB];
    #pragma unroll
    for (int r = 0; r < RPB; r++) { Z[r] = 0.f; S[r] = 0.f; WX[r] = 0.f; }

    #pragma unroll 1
    for (int it = 0; it < ITERS; it++) {
        // Front-batch all 7 LDG.128 (rows at fixed 8192-quad strides).
        float4 xr[RPB];
        #pragma unroll
        for (int r = 0; r < RPB; r++)
            xr[r] = __ldg(plg + (size_t)r * (C_CELLS / 4));
        const float4 gx = __ldg(pct + 0);
        const float4 gy = __ldg(pct + 1);
        const float4 gz = __ldg(pct + 2);
        pct += 3 * THREADS;
        plg += THREADS;

        // Arrayless per-element body: direct float4 components.
        #pragma unroll
        for (int r = 0; r < RPB; r++) {
            const float nxr = nx[r], nyr = ny[r], nzr = nz[r];

            #define ELEM(X, GX, GY, GZ)                                        \
            {                                                                  \
                const float x_ = (X);                                          \
                Z[r] += fexp2_ap(x_ * LOG2E);                                   \
                float a_ = fmaf(nxr, (GX), fmaf(nyr, (GY),                      \
                           fmaf(nzr, (GZ), HALFK)));                            \
                float w_ = fexp2_ap(-fsqrt_ap(fabsf(a_)));                      \
                S[r]  += w_;                                                    \
                WX[r]  = fmaf(w_, x_, WX[r]);                                   \
            }

            ELEM(xr[r].x, gx.x, gy.x, gz.x)
            ELEM(xr[r].y, gx.y, gy.y, gz.y)
            ELEM(xr[r].z, gx.z, gy.z, gz.z)
            ELEM(xr[r].w, gx.w, gy.w, gz.w)
            #undef ELEM
        }
    }

    // ---- Block reduction of 12 accumulators (deterministic tree) ----
    float acc[3 * RPB];
    #pragma unroll
    for (int r = 0; r < RPB; r++) {
        acc[r * 3 + 0] = Z[r]; acc[r * 3 + 1] = S[r]; acc[r * 3 + 2] = WX[r];
    }
    __shared__ float red[3 * RPB][NWARPS];
    const int lane = tid & 31, warp = tid >> 5;
    #pragma unroll
    for (int i = 0; i < 3 * RPB; i++) {
        float vv = acc[i];
        #pragma unroll
        for (int o = 16; o > 0; o >>= 1) vv += __shfl_down_sync(0xffffffffu, vv, o);
        if (lane == 0) red[i][warp] = vv;
    }
    __syncthreads();
    if (tid < 3 * RPB) {
        float vv = 0.f;
        #pragma unroll
        for (int wi = 0; wi < NWARPS; wi++) vv += red[tid][wi];
        const int r     = tid / 3;
        const int which = tid % 3;
        const int idx   = (row0 + r) * SPLIT + ch;
        if      (which == 0) d_pZ[idx] = vv;
        else if (which == 1) d_pS[idx] = vv;
        else                 d_pW[idx] = vv;
    }

    // ---- Last block reduces everything ----
    __shared__ bool isLast;
    __syncthreads();
    if (tid == 0) {
        __threadfence();
        unsigned int t = atomicAdd(&d_ctr, 1u);
        isLast = (t == (unsigned int)(GRID - 1));
    }
    __syncthreads();

    if (isLast) {
        float v = 0.f;
        #pragma unroll
        for (int half = 0; half < B_ROWS / THREADS; half++) {   // 2 rows/thread
            const int b = tid + half * THREADS;
            float Zt = 0.f, St = 0.f, Wt = 0.f;
            #pragma unroll
            for (int cc = 0; cc < SPLIT; cc++) {
                Zt += __ldcg(&d_pZ[b * SPLIT + cc]);
                St += __ldcg(&d_pS[b * SPLIT + cc]);
                Wt += __ldcg(&d_pW[b * SPLIT + cc]);
            }
            v += logf(Zt) - Wt * __fdividef(1.0f, St);
        }
        __shared__ float fin[NWARPS];
        #pragma unroll
        for (int o = 16; o > 0; o >>= 1) v += __shfl_down_sync(0xffffffffu, v, o);
        if (lane == 0) fin[warp] = v;
        __syncthreads();
        if (tid == 0) {
            float s = 0.f;
            #pragma unroll
            for (int i = 0; i < NWARPS; i++) s += fin[i];
            out[0] = s * (1.0f / (float)B_ROWS);
            d_ctr  = 0;   // reset for graph replay
        }
    }
}

extern "C" void kernel_launch(void* const* d_in, const int* in_sizes, int n_in,
                              void* d_out, int out_size) {
    const float* logits = (const float*)d_in[0];   // [512, 32768]
    const float* latlon = (const float*)d_in[1];   // [512, 2]
    const float* geo    = (const float*)d_in[2];   // [32768, 2]

    precompute<<<(C_CELLS + 255) / 256, 256>>>(geo, latlon);
    main_kernel<<<GRID, THREADS>>>(logits, (float*)d_out);
}